// round 13
// baseline (speedup 1.0000x reference)
#include <cuda_runtime.h>
#include <cuda_bf16.h>
#include <math.h>
#include <stdint.h>

#define NTOK   32768
#define CDIM   256
#define SCODE  1024
#define HW     1024
#define BETA   0.25f

// certified bounds: |w| <= 2^-10, |w - bf16(w)| <= 2^-9 * 2^-10 = 2^-19
#define WMAX   9.765625e-4f
#define WLOMAX 1.9073486e-6f

// ======================= device scratch ====================================
__device__ float          g_w2[SCODE];
__device__ float          g_x2[NTOK];      // exact x2 (reference chain)
__device__ float          g_sa[NTOK];      // sum |x - bf16(x)|  (bound)
__device__ float          g_sh[NTOK];      // sum |bf16(x)|      (bound)
__device__ int            g_idx[NTOK];
__device__ unsigned int   g_hist[SCODE];
__device__ float          g_losspart[512];
__device__ __nv_bfloat16  g_xhi[NTOK * CDIM];   // [tok][k]
__device__ __nv_bfloat16  g_ehi[SCODE * CDIM];  // [code][k]
__device__ float          g_scores[(size_t)NTOK * SCODE];   // 128 MB
__device__ int            g_cand[NTOK * 16];
__device__ int            g_cnt [NTOK];

// ======================= small helpers =====================================
__device__ __forceinline__ uint32_t smem_u32(const void* p) {
    uint32_t a;
    asm("{ .reg .u64 t; cvta.to.shared.u64 t, %1; cvt.u32.u64 %0, t; }" : "=r"(a) : "l"(p));
    return a;
}
__device__ __forceinline__ void ldsm4(uint32_t& r0, uint32_t& r1, uint32_t& r2, uint32_t& r3,
                                      uint32_t addr) {
    asm volatile("ldmatrix.sync.aligned.m8n8.x4.shared.b16 {%0,%1,%2,%3}, [%4];"
                 : "=r"(r0), "=r"(r1), "=r"(r2), "=r"(r3) : "r"(addr));
}
__device__ __forceinline__ void mma16816(float* c, const uint32_t* a, uint32_t b0, uint32_t b1) {
    asm volatile("mma.sync.aligned.m16n8k16.row.col.f32.bf16.bf16.f32 "
                 "{%0,%1,%2,%3}, {%4,%5,%6,%7}, {%8,%9}, {%0,%1,%2,%3};"
                 : "+f"(c[0]), "+f"(c[1]), "+f"(c[2]), "+f"(c[3])
                 : "r"(a[0]), "r"(a[1]), "r"(a[2]), "r"(a[3]), "r"(b0), "r"(b1));
}
// swizzled byte offset in a [row][256 bf16] tile (512B rows, 16B granules)
__device__ __forceinline__ uint32_t swz(int row, int k) {   // k multiple of 8
    int ch = k >> 3;   // 0..31
    return (uint32_t)(row * 512 + ((ch >> 3) << 7) + (((ch & 7) ^ (row & 7)) << 4));
}
__device__ __forceinline__ float ulp_of(float v) {
    return __uint_as_float(__float_as_uint(v) & 0x7f800000u) * 1.1920929e-7f;
}

// ======================= kernel: init (w2 exact, zero, emb->bf16) ==========
// grid 128 x 256 = 32768 threads
__global__ void k_init(const float* __restrict__ emb) {
    int t = blockIdx.x * 256 + threadIdx.x;   // 0..32767
    // emb bf16 convert: 8 elements per thread
    {
        float4 a = *(const float4*)(emb + (size_t)t * 8);
        float4 b = *(const float4*)(emb + (size_t)t * 8 + 4);
        __nv_bfloat162 r[4];
        r[0] = __nv_bfloat162(__float2bfloat16(a.x), __float2bfloat16(a.y));
        r[1] = __nv_bfloat162(__float2bfloat16(a.z), __float2bfloat16(a.w));
        r[2] = __nv_bfloat162(__float2bfloat16(b.x), __float2bfloat16(b.y));
        r[3] = __nv_bfloat162(__float2bfloat16(b.z), __float2bfloat16(b.w));
        *(uint4*)(g_ehi + (size_t)t * 8) = *(uint4*)r;
    }
    if (t < SCODE) {
        const float* row = emb + (size_t)t * CDIM;
        float s = 0.f;
        for (int k = 0; k < CDIM; k++) s = __fadd_rn(s, __fmul_rn(row[k], row[k]));
        g_w2[t] = s;
        g_hist[t] = 0u;
    }
    if (t < 512) g_losspart[t] = 0.f;
}

// ======================= kernel: x prep (transpose, x2 exact, bounds) ======
// grid (32 hw-tiles, 32 batches), 256 threads. Block = 32 tokens x all 256 c.
__global__ void __launch_bounds__(256) k_pre(const float* __restrict__ x) {
    __shared__ float tile[256][33];          // [c][tok], pad 33 -> conflict-free
    __shared__ float psa[32][8], psh[32][8];
    const int tid = threadIdx.x;
    const int b = blockIdx.y, hw0 = blockIdx.x * 32;
    const int tok_base = b * HW + hw0;

    // load: warp w covers c = i*8 + w, 128B coalesced rows
    const float* xb = x + (size_t)b * CDIM * HW + hw0;
    const int wc = tid >> 5, lh = tid & 31;
#pragma unroll 8
    for (int i = 0; i < 32; i++)
        tile[i * 8 + wc][lh] = xb[(size_t)(i * 8 + wc) * HW + lh];
    __syncthreads();

    // bf16 transpose write + margin partials: 8 threads per token, 32 c each
    {
        const int tok = tid >> 3, c0 = (tid & 7) * 32;
        float sa = 0.f, sh = 0.f;
        __nv_bfloat16 hb[32];
#pragma unroll
        for (int j = 0; j < 32; j++) {
            float v = tile[c0 + j][tok];
            __nv_bfloat16 h = __float2bfloat16(v);
            float hf = __bfloat162float(h);
            hb[j] = h;
            sa += fabsf(v - hf);
            sh += fabsf(hf);
        }
        uint4* dst = (uint4*)(g_xhi + (size_t)(tok_base + tok) * CDIM + c0);
        const uint4* src = (const uint4*)hb;
#pragma unroll
        for (int j = 0; j < 4; j++) dst[j] = src[j];
        psa[tok][tid & 7] = sa;
        psh[tok][tid & 7] = sh;
    }
    __syncthreads();

    // exact x2 chain (reference order) per token, warp 0
    if (tid < 32) {
        float s = 0.f;
        for (int c = 0; c < CDIM; c++) {
            float v = tile[c][tid];
            s = __fadd_rn(s, __fmul_rn(v, v));
        }
        g_x2[tok_base + tid] = s;
        float a = 0.f, h = 0.f;
#pragma unroll
        for (int j = 0; j < 8; j++) { a += psa[tid][j]; h += psh[tid][j]; }
        g_sa[tok_base + tid] = a;
        g_sh[tok_base + tid] = h;
    }
}

// ======================= kernel: HMMA GEMM + min + candidate collect =======
// 256 blocks x 256 threads (8 warps); 128 tokens/block; 16 code tiles of 64.
#define SA    0
#define SB0   65536
#define SB1   98304
#define SW2   131072
#define SMIN  135168
#define SMEM_SZ 135680

__global__ void __launch_bounds__(256, 1) k_mma() {
    extern __shared__ char smem[];
    const uint32_t sb = smem_u32(smem);
    const int tid  = threadIdx.x;
    const int wid  = tid >> 5;
    const int lane = tid & 31;
    const int n0   = blockIdx.x * 128;
    const int tw   = wid * 16;                    // warp's token base within block
    float* w2s  = (float*)(smem + SW2);
    float* smin = (float*)(smem + SMIN);

    // load A (x_hi 128x256 bf16, swizzled)
#pragma unroll
    for (int i = 0; i < 16; i++) {
        int v = i * 256 + tid;                    // 0..4095
        int row = v >> 5, ch = v & 31;
        uint4 d = *(const uint4*)(g_xhi + (size_t)(n0 + row) * CDIM + ch * 8);
        *(uint4*)(smem + SA + swz(row, ch * 8)) = d;
    }
    // load B tile 0
#pragma unroll
    for (int i = 0; i < 8; i++) {
        int v = i * 256 + tid;                    // 0..2047
        int row = v >> 5, ch = v & 31;
        uint4 d = *(const uint4*)(g_ehi + (size_t)row * CDIM + ch * 8);
        *(uint4*)(smem + SB0 + swz(row, ch * 8)) = d;
    }
    // w2 -> smem, min init
#pragma unroll
    for (int i = 0; i < 4; i++) w2s[tid + i * 256] = g_w2[tid + i * 256];
    if (tid < 128) smin[tid] = 3.4e38f;
    __syncthreads();

    // ldmatrix lane addressing (constant per lane)
    const int arow = tw + (lane & 15);
    const int akof = (lane >> 4) << 3;
    const int brow = (lane & 7) + ((lane >> 4) << 3);   // + g*16
    const int bkof = ((lane >> 3) & 1) << 3;
    // epilogue addressing
    const int r4 = lane >> 2;            // 0..7
    const int c2 = (lane & 3) * 2;

    for (int t = 0; t < 16; t++) {
        char* B = smem + ((t & 1) ? SB1 : SB0);
        // stage next B tile into registers (hidden under compute)
        uint4 st[8];
        if (t < 15) {
#pragma unroll
            for (int i = 0; i < 8; i++) {
                int v = i * 256 + tid;
                int row = v >> 5, ch = v & 31;
                st[i] = *(const uint4*)(g_ehi + (size_t)((t + 1) * 64 + row) * CDIM + ch * 8);
            }
        }

        float acc[8][4];
#pragma unroll
        for (int g = 0; g < 8; g++)
#pragma unroll
            for (int j = 0; j < 4; j++) acc[g][j] = 0.f;

#pragma unroll
        for (int ks = 0; ks < 16; ks++) {
            uint32_t a[4];
            ldsm4(a[0], a[1], a[2], a[3], sb + SA + swz(arow, ks * 16 + akof));
#pragma unroll
            for (int g = 0; g < 4; g++) {
                uint32_t b0, b1, b2, b3;
                ldsm4(b0, b1, b2, b3,
                      sb + (uint32_t)(B - smem) + swz(g * 16 + brow, ks * 16 + bkof));
                mma16816(acc[2 * g],     a, b0, b1);
                mma16816(acc[2 * g + 1], a, b2, b3);
            }
        }

        // epilogue: s = w2 - 2*dot -> gmem scores + running per-token min
        {
            const int cb = t * 64;
            float* s0 = g_scores + (size_t)(n0 + tw + r4) * SCODE + cb;
            float* s1 = g_scores + (size_t)(n0 + tw + r4 + 8) * SCODE + cb;
            float m0 = 3.4e38f, m1 = 3.4e38f;
#pragma unroll
            for (int g = 0; g < 8; g++) {
                int col = g * 8 + c2;
                float w0 = w2s[cb + col], w1 = w2s[cb + col + 1];
                float2 v0 = { w0 - 2.f * acc[g][0], w1 - 2.f * acc[g][1] };
                float2 v1 = { w0 - 2.f * acc[g][2], w1 - 2.f * acc[g][3] };
                *(float2*)(s0 + col) = v0;
                *(float2*)(s1 + col) = v1;
                m0 = fminf(m0, fminf(v0.x, v0.y));
                m1 = fminf(m1, fminf(v1.x, v1.y));
            }
            // reduce over the 4 lanes sharing this r4
            m0 = fminf(m0, __shfl_xor_sync(~0u, m0, 1));
            m0 = fminf(m0, __shfl_xor_sync(~0u, m0, 2));
            m1 = fminf(m1, __shfl_xor_sync(~0u, m1, 1));
            m1 = fminf(m1, __shfl_xor_sync(~0u, m1, 2));
            if ((lane & 3) == 0) {
                smin[tw + r4]     = fminf(smin[tw + r4], m0);
                smin[tw + r4 + 8] = fminf(smin[tw + r4 + 8], m1);
            }
        }

        // commit staged B, barrier
        if (t < 15) {
            char* Bn = smem + ((t & 1) ? SB0 : SB1);
#pragma unroll
            for (int i = 0; i < 8; i++) {
                int v = i * 256 + tid;
                int row = v >> 5, ch = v & 31;
                *(uint4*)(Bn + swz(row, ch * 8)) = st[i];
            }
            __syncthreads();
        }
    }
    __syncthreads();   // scores + smin visible block-wide

    // phase 2: candidate collection vs final min (scores mostly L2-hot)
    for (int i = 0; i < 16; i++) {
        const int tok = tw + i;
        const int n = n0 + tok;
        float x2 = g_x2[n];
        float gg = ulp_of(x2 + 0.25f);
        float marg = 2.f * gg + 2.004f * (WMAX * g_sa[n] + WLOMAX * g_sh[n]) + 1e-5f;
        const float thr = smin[tok] + marg;
        const float4* sp = (const float4*)(g_scores + (size_t)n * SCODE);
        int cnt = 0;
#pragma unroll
        for (int c = 0; c < 8; c++) {
            float4 v = sp[c * 32 + lane];
            float vv[4] = {v.x, v.y, v.z, v.w};
#pragma unroll
            for (int q = 0; q < 4; q++) {
                bool p = vv[q] < thr;
                unsigned m = __ballot_sync(~0u, p);
                if (p) {
                    int pos = cnt + __popc(m & ((1u << lane) - 1u));
                    if (pos < 16) g_cand[(size_t)n * 16 + pos] = c * 128 + lane * 4 + q;
                }
                cnt += __popc(m);
            }
        }
        if (lane == 0) g_cnt[n] = (cnt > 16) ? 1000 : cnt;
    }
}

// ======================= kernel: exact recompute, warp-per-token ===========
// lane l owns candidate l: full serial ascending-k fmaf chain (bit-exact);
// x loads are warp-uniform (broadcast), e loads contiguous per lane.
__global__ void __launch_bounds__(256) k_exact(const float* __restrict__ x,
                                               const float* __restrict__ emb) {
    const int n = blockIdx.x * 8 + (threadIdx.x >> 5);
    const int lane = threadIdx.x & 31;
    const int b = n >> 10, hw = n & 1023;
    const float* xp = x + (size_t)b * CDIM * HW + hw;
    const int cnt = g_cnt[n];
    float q; int ss;

    if (cnt <= 16) {
        const bool active = lane < cnt;
        ss = g_cand[(size_t)n * 16 + (active ? lane : 0)];
        const float* e = emb + (size_t)ss * CDIM;
        float d = 0.f;
        for (int kc = 0; kc < CDIM; kc += 8) {
            float xv[8];
#pragma unroll
            for (int j = 0; j < 8; j++) xv[j] = __ldg(xp + (size_t)(kc + j) * HW);
            float4 e0 = *(const float4*)(e + kc);
            float4 e1 = *(const float4*)(e + kc + 4);
            d = fmaf(xv[0], e0.x, d); d = fmaf(xv[1], e0.y, d);
            d = fmaf(xv[2], e0.z, d); d = fmaf(xv[3], e0.w, d);
            d = fmaf(xv[4], e1.x, d); d = fmaf(xv[5], e1.y, d);
            d = fmaf(xv[6], e1.z, d); d = fmaf(xv[7], e1.w, d);
        }
        float x2 = g_x2[n];
        q = __fadd_rn(__fadd_rn(x2, -__fmul_rn(2.f, d)), g_w2[ss]);
        if (!active) { q = 3.4e38f; ss = SCODE; }
    } else {
        // fallback: full exact scan, lane strided (expected never)
        float x2 = g_x2[n];
        q = 3.4e38f; ss = SCODE;
        for (int s0 = lane; s0 < SCODE; s0 += 32) {
            const float* e = emb + (size_t)s0 * CDIM;
            float d = 0.f;
            for (int k = 0; k < CDIM; k++) d = fmaf(__ldg(xp + (size_t)k * HW), e[k], d);
            float qq = __fadd_rn(__fadd_rn(x2, -__fmul_rn(2.f, d)), g_w2[s0]);
            if (qq < q || (qq == q && s0 < ss)) { q = qq; ss = s0; }
        }
    }
    // warp lex-min reduce on (q, ss): first-min (lowest index) tie-break
#pragma unroll
    for (int o = 16; o > 0; o >>= 1) {
        float q2 = __shfl_xor_sync(~0u, q, o);
        int   s2 = __shfl_xor_sync(~0u, ss, o);
        if (q2 < q || (q2 == q && s2 < ss)) { q = q2; ss = s2; }
    }
    if (lane == 0) {
        g_idx[n] = ss;
        atomicAdd(&g_hist[ss], 1u);
    }
}

// ======================= kernel: gather + ST write + loss ==================
__global__ void k_gather(const float* __restrict__ x, const float* __restrict__ emb,
                         float* __restrict__ out) {
    const int n0  = blockIdx.x * 64;
    const int b   = n0 >> 10;
    const int hw0 = n0 & 1023;
    const int tok = threadIdx.x & 63;
    const int cc  = threadIdx.x >> 6;

    const int mi = g_idx[n0 + tok];
    const float* e = emb + (size_t)mi * CDIM;
    const size_t base = (size_t)b * (CDIM * HW) + hw0 + tok;

    float s = 0.f;
    for (int c = cc; c < CDIM; c += 4) {
        float v = __ldg(e + c);
        size_t off = base + (size_t)c * HW;
        float xv = x[off];
        float diff = __fadd_rn(v, -xv);
        out[off] = __fadd_rn(xv, diff);
        s = fmaf(diff, diff, s);
    }
    __shared__ float red[256];
    red[threadIdx.x] = s;
    __syncthreads();
    for (int st = 128; st > 0; st >>= 1) {
        if (threadIdx.x < st) red[threadIdx.x] += red[threadIdx.x + st];
        __syncthreads();
    }
    if (threadIdx.x == 0) g_losspart[blockIdx.x] = red[0];
}

// ======================= kernel: finalize ==================================
__global__ void k_final(float* __restrict__ out, int out_size) {
    __shared__ float red[1024];
    const int t = threadIdx.x;
    float p = (float)g_hist[t] / (float)NTOK;
    red[t] = p * logf(p + 1e-6f);
    __syncthreads();
    for (int st = 512; st > 0; st >>= 1) {
        if (t < st) red[t] += red[t + st];
        __syncthreads();
    }
    float plogp = red[0];
    __syncthreads();
    red[t] = (t < 512) ? g_losspart[t] : 0.f;
    __syncthreads();
    for (int st = 512; st > 0; st >>= 1) {
        if (t < st) red[t] += red[t + st];
        __syncthreads();
    }
    if (t == 0) {
        out[out_size - 2] = BETA * (red[0] / (float)(NTOK * CDIM));
        out[out_size - 1] = expf(-plogp);
    }
}

// ======================= launch ============================================
extern "C" void kernel_launch(void* const* d_in, const int* in_sizes, int n_in,
                              void* d_out, int out_size) {
    const float* x   = (const float*)d_in[0];   // [32,256,32,32]
    const float* emb = (const float*)d_in[1];   // [1024,256]
    float* out = (float*)d_out;

    k_init<<<128, 256>>>(emb);
    k_pre<<<dim3(32, 32), 256>>>(x);

    cudaFuncSetAttribute(k_mma, cudaFuncAttributeMaxDynamicSharedMemorySize, SMEM_SZ);
    k_mma<<<NTOK / 128, 256, SMEM_SZ>>>();

    k_exact<<<NTOK / 8, 256>>>(x, emb);
    k_gather<<<NTOK / 64, 256>>>(x, emb, out);
    k_final<<<1, 1024>>>(out, out_size);
}

// round 15
// speedup vs baseline: 1.1167x; 1.1167x over previous
#include <cuda_runtime.h>
#include <cuda_bf16.h>
#include <math.h>
#include <stdint.h>

#define NTOK   32768
#define CDIM   256
#define SCODE  1024
#define HW     1024
#define BETA   0.25f

// certified bounds: |w| <= 2^-10, |w - bf16(w)| <= 2^-9 * 2^-10 = 2^-19
#define WMAX   9.765625e-4f
#define WLOMAX 1.9073486e-6f

// ======================= device scratch ====================================
__device__ float          g_w2[SCODE];
__device__ float          g_x2[NTOK];      // exact x2 (reference chain)
__device__ float          g_sa[NTOK];      // sum |x - bf16(x)|  (bound)
__device__ float          g_sh[NTOK];      // sum |bf16(x)|      (bound)
__device__ int            g_idx[NTOK];
__device__ unsigned int   g_hist[SCODE];
__device__ float          g_losspart[512];
__device__ __nv_bfloat16  g_xhi[NTOK * CDIM];   // [tok][k]
__device__ __nv_bfloat16  g_ehi[SCODE * CDIM];  // [code][k]
__device__ float          g_scores[(size_t)NTOK * SCODE];   // 128 MB
__device__ int            g_cand[NTOK * 16];
__device__ int            g_cnt [NTOK];

// ======================= small helpers =====================================
__device__ __forceinline__ uint32_t smem_u32(const void* p) {
    uint32_t a;
    asm("{ .reg .u64 t; cvta.to.shared.u64 t, %1; cvt.u32.u64 %0, t; }" : "=r"(a) : "l"(p));
    return a;
}
__device__ __forceinline__ void ldsm4(uint32_t& r0, uint32_t& r1, uint32_t& r2, uint32_t& r3,
                                      uint32_t addr) {
    asm volatile("ldmatrix.sync.aligned.m8n8.x4.shared.b16 {%0,%1,%2,%3}, [%4];"
                 : "=r"(r0), "=r"(r1), "=r"(r2), "=r"(r3) : "r"(addr));
}
__device__ __forceinline__ void mma16816(float* c, const uint32_t* a, uint32_t b0, uint32_t b1) {
    asm volatile("mma.sync.aligned.m16n8k16.row.col.f32.bf16.bf16.f32 "
                 "{%0,%1,%2,%3}, {%4,%5,%6,%7}, {%8,%9}, {%0,%1,%2,%3};"
                 : "+f"(c[0]), "+f"(c[1]), "+f"(c[2]), "+f"(c[3])
                 : "r"(a[0]), "r"(a[1]), "r"(a[2]), "r"(a[3]), "r"(b0), "r"(b1));
}
// swizzled byte offset in a [row][256 bf16] tile (512B rows, 16B granules)
__device__ __forceinline__ uint32_t swz(int row, int k) {   // k multiple of 8
    int ch = k >> 3;   // 0..31
    return (uint32_t)(row * 512 + ((ch >> 3) << 7) + (((ch & 7) ^ (row & 7)) << 4));
}
__device__ __forceinline__ float ulp_of(float v) {
    return __uint_as_float(__float_as_uint(v) & 0x7f800000u) * 1.1920929e-7f;
}

// ======================= kernel: init (w2 exact, zero, emb->bf16) ==========
// grid 128 x 256 = 32768 threads
__global__ void k_init(const float* __restrict__ emb) {
    int t = blockIdx.x * 256 + threadIdx.x;   // 0..32767
    // emb bf16 convert: 8 elements per thread
    {
        float4 a = *(const float4*)(emb + (size_t)t * 8);
        float4 b = *(const float4*)(emb + (size_t)t * 8 + 4);
        __nv_bfloat162 r[4];
        r[0] = __nv_bfloat162(__float2bfloat16(a.x), __float2bfloat16(a.y));
        r[1] = __nv_bfloat162(__float2bfloat16(a.z), __float2bfloat16(a.w));
        r[2] = __nv_bfloat162(__float2bfloat16(b.x), __float2bfloat16(b.y));
        r[3] = __nv_bfloat162(__float2bfloat16(b.z), __float2bfloat16(b.w));
        *(uint4*)(g_ehi + (size_t)t * 8) = *(uint4*)r;
    }
    if (t < SCODE) {
        const float* row = emb + (size_t)t * CDIM;
        float s = 0.f;
        for (int k = 0; k < CDIM; k++) s = __fadd_rn(s, __fmul_rn(row[k], row[k]));
        g_w2[t] = s;
        g_hist[t] = 0u;
    }
    if (t < 512) g_losspart[t] = 0.f;
}

// ======================= kernel: x prep (transpose, x2 exact, bounds) ======
// grid (32 hw-tiles, 32 batches), 256 threads. Block = 32 tokens x all 256 c.
__global__ void __launch_bounds__(256) k_pre(const float* __restrict__ x) {
    __shared__ float tile[256][33];          // [c][tok], pad 33 -> conflict-free
    __shared__ float psa[32][8], psh[32][8];
    const int tid = threadIdx.x;
    const int b = blockIdx.y, hw0 = blockIdx.x * 32;
    const int tok_base = b * HW + hw0;

    // load: warp w covers c = i*8 + w, 128B coalesced rows
    const float* xb = x + (size_t)b * CDIM * HW + hw0;
    const int wc = tid >> 5, lh = tid & 31;
#pragma unroll 8
    for (int i = 0; i < 32; i++)
        tile[i * 8 + wc][lh] = xb[(size_t)(i * 8 + wc) * HW + lh];
    __syncthreads();

    // bf16 transpose write + margin partials: 8 threads per token, 32 c each
    {
        const int tok = tid >> 3, c0 = (tid & 7) * 32;
        float sa = 0.f, sh = 0.f;
        __nv_bfloat16 hb[32];
#pragma unroll
        for (int j = 0; j < 32; j++) {
            float v = tile[c0 + j][tok];
            __nv_bfloat16 h = __float2bfloat16(v);
            float hf = __bfloat162float(h);
            hb[j] = h;
            sa += fabsf(v - hf);
            sh += fabsf(hf);
        }
        uint4* dst = (uint4*)(g_xhi + (size_t)(tok_base + tok) * CDIM + c0);
        const uint4* src = (const uint4*)hb;
#pragma unroll
        for (int j = 0; j < 4; j++) dst[j] = src[j];
        psa[tok][tid & 7] = sa;
        psh[tok][tid & 7] = sh;
    }
    __syncthreads();

    // exact x2 chain (reference order) per token, warp 0
    if (tid < 32) {
        float s = 0.f;
        for (int c = 0; c < CDIM; c++) {
            float v = tile[c][tid];
            s = __fadd_rn(s, __fmul_rn(v, v));
        }
        g_x2[tok_base + tid] = s;
        float a = 0.f, h = 0.f;
#pragma unroll
        for (int j = 0; j < 8; j++) { a += psa[tid][j]; h += psh[tid][j]; }
        g_sa[tok_base + tid] = a;
        g_sh[tok_base + tid] = h;
    }
}

// ======================= kernel: HMMA GEMM + min + candidate collect =======
// 256 blocks x 256 threads (8 warps); 128 tokens/block; 16 code tiles of 64.
#define SA    0
#define SB0   65536
#define SB1   98304
#define SW2   131072
#define SMIN  135168
#define SMEM_SZ 135680

__global__ void __launch_bounds__(256, 1) k_mma() {
    extern __shared__ char smem[];
    const uint32_t sb = smem_u32(smem);
    const int tid  = threadIdx.x;
    const int wid  = tid >> 5;
    const int lane = tid & 31;
    const int n0   = blockIdx.x * 128;
    const int tw   = wid * 16;                    // warp's token base within block
    float* w2s  = (float*)(smem + SW2);
    float* smin = (float*)(smem + SMIN);

    // load A (x_hi 128x256 bf16, swizzled)
#pragma unroll
    for (int i = 0; i < 16; i++) {
        int v = i * 256 + tid;                    // 0..4095
        int row = v >> 5, ch = v & 31;
        uint4 d = *(const uint4*)(g_xhi + (size_t)(n0 + row) * CDIM + ch * 8);
        *(uint4*)(smem + SA + swz(row, ch * 8)) = d;
    }
    // load B tile 0
#pragma unroll
    for (int i = 0; i < 8; i++) {
        int v = i * 256 + tid;                    // 0..2047
        int row = v >> 5, ch = v & 31;
        uint4 d = *(const uint4*)(g_ehi + (size_t)row * CDIM + ch * 8);
        *(uint4*)(smem + SB0 + swz(row, ch * 8)) = d;
    }
    // w2 -> smem, min init
#pragma unroll
    for (int i = 0; i < 4; i++) w2s[tid + i * 256] = g_w2[tid + i * 256];
    if (tid < 128) smin[tid] = 3.4e38f;
    __syncthreads();

    // ldmatrix lane addressing (constant per lane)
    const int arow = tw + (lane & 15);
    const int akof = (lane >> 4) << 3;
    const int brow = (lane & 7) + ((lane >> 4) << 3);   // + g*16
    const int bkof = ((lane >> 3) & 1) << 3;
    // epilogue addressing
    const int r4 = lane >> 2;            // 0..7
    const int c2 = (lane & 3) * 2;

    for (int t = 0; t < 16; t++) {
        char* B = smem + ((t & 1) ? SB1 : SB0);
        // stage next B tile into registers (hidden under compute)
        uint4 st[8];
        if (t < 15) {
#pragma unroll
            for (int i = 0; i < 8; i++) {
                int v = i * 256 + tid;
                int row = v >> 5, ch = v & 31;
                st[i] = *(const uint4*)(g_ehi + (size_t)((t + 1) * 64 + row) * CDIM + ch * 8);
            }
        }

        float acc[8][4];
#pragma unroll
        for (int g = 0; g < 8; g++)
#pragma unroll
            for (int j = 0; j < 4; j++) acc[g][j] = 0.f;

#pragma unroll
        for (int ks = 0; ks < 16; ks++) {
            uint32_t a[4];
            ldsm4(a[0], a[1], a[2], a[3], sb + SA + swz(arow, ks * 16 + akof));
#pragma unroll
            for (int g = 0; g < 4; g++) {
                uint32_t b0, b1, b2, b3;
                ldsm4(b0, b1, b2, b3,
                      sb + (uint32_t)(B - smem) + swz(g * 16 + brow, ks * 16 + bkof));
                mma16816(acc[2 * g],     a, b0, b1);
                mma16816(acc[2 * g + 1], a, b2, b3);
            }
        }

        // epilogue: s = w2 - 2*dot -> gmem scores + running per-token min
        {
            const int cb = t * 64;
            float* s0 = g_scores + (size_t)(n0 + tw + r4) * SCODE + cb;
            float* s1 = g_scores + (size_t)(n0 + tw + r4 + 8) * SCODE + cb;
            float m0 = 3.4e38f, m1 = 3.4e38f;
#pragma unroll
            for (int g = 0; g < 8; g++) {
                int col = g * 8 + c2;
                float w0 = w2s[cb + col], w1 = w2s[cb + col + 1];
                float2 v0 = { w0 - 2.f * acc[g][0], w1 - 2.f * acc[g][1] };
                float2 v1 = { w0 - 2.f * acc[g][2], w1 - 2.f * acc[g][3] };
                *(float2*)(s0 + col) = v0;
                *(float2*)(s1 + col) = v1;
                m0 = fminf(m0, fminf(v0.x, v0.y));
                m1 = fminf(m1, fminf(v1.x, v1.y));
            }
            // reduce over the 4 lanes sharing this r4
            m0 = fminf(m0, __shfl_xor_sync(~0u, m0, 1));
            m0 = fminf(m0, __shfl_xor_sync(~0u, m0, 2));
            m1 = fminf(m1, __shfl_xor_sync(~0u, m1, 1));
            m1 = fminf(m1, __shfl_xor_sync(~0u, m1, 2));
            if ((lane & 3) == 0) {
                smin[tw + r4]     = fminf(smin[tw + r4], m0);
                smin[tw + r4 + 8] = fminf(smin[tw + r4 + 8], m1);
            }
        }

        // commit staged B, barrier
        if (t < 15) {
            char* Bn = smem + ((t & 1) ? SB0 : SB1);
#pragma unroll
            for (int i = 0; i < 8; i++) {
                int v = i * 256 + tid;
                int row = v >> 5, ch = v & 31;
                *(uint4*)(Bn + swz(row, ch * 8)) = st[i];
            }
            __syncthreads();
        }
    }
    __syncthreads();   // scores + smin visible block-wide

    // phase 2: candidate collection vs final min (scores mostly L2-hot)
    for (int i = 0; i < 16; i++) {
        const int tok = tw + i;
        const int n = n0 + tok;
        float x2 = g_x2[n];
        float gg = ulp_of(x2 + 0.25f);
        float marg = 2.f * gg + 2.004f * (WMAX * g_sa[n] + WLOMAX * g_sh[n]) + 1e-5f;
        const float thr = smin[tok] + marg;
        const float4* sp = (const float4*)(g_scores + (size_t)n * SCODE);
        int cnt = 0;
#pragma unroll
        for (int c = 0; c < 8; c++) {
            float4 v = sp[c * 32 + lane];
            float vv[4] = {v.x, v.y, v.z, v.w};
#pragma unroll
            for (int q = 0; q < 4; q++) {
                bool p = vv[q] < thr;
                unsigned m = __ballot_sync(~0u, p);
                if (p) {
                    int pos = cnt + __popc(m & ((1u << lane) - 1u));
                    if (pos < 16) g_cand[(size_t)n * 16 + pos] = c * 128 + lane * 4 + q;
                }
                cnt += __popc(m);
            }
        }
        if (lane == 0) g_cnt[n] = (cnt > 16) ? 1000 : cnt;
    }
}

// ======================= kernel: exact recompute, warp-per-token ===========
// x staged via smem (full-sector coalesced loads, broadcast reads);
// lane l owns candidate l: serial ascending-k fmaf chain (bit-exact).
__global__ void __launch_bounds__(256) k_exact(const float* __restrict__ x,
                                               const float* __restrict__ emb) {
    __shared__ float sx[8][256];
    const int tid = threadIdx.x;
    const int wid = tid >> 5;
    const int lane = tid & 31;
    const int nb = blockIdx.x * 8;            // 8 consecutive tokens (same batch)
    const int b = nb >> 10, hw0 = nb & 1023;

    // stage x: thread c loads x[b, c, hw0..hw0+7] (one full 32B sector)
    {
        const float* xp = x + ((size_t)b * CDIM + tid) * HW + hw0;
        float4 v0 = *(const float4*)(xp);
        float4 v1 = *(const float4*)(xp + 4);
        sx[0][tid] = v0.x; sx[1][tid] = v0.y; sx[2][tid] = v0.z; sx[3][tid] = v0.w;
        sx[4][tid] = v1.x; sx[5][tid] = v1.y; sx[6][tid] = v1.z; sx[7][tid] = v1.w;
    }
    __syncthreads();

    const int n = nb + wid;
    const float* xr = sx[wid];
    const int cnt = g_cnt[n];
    float q; int ss;

    if (cnt <= 16) {
        const bool active = lane < cnt;
        ss = g_cand[(size_t)n * 16 + (active ? lane : 0)];
        const float* e = emb + (size_t)ss * CDIM;
        float d = 0.f;
        for (int kc = 0; kc < CDIM; kc += 8) {
            float4 x0 = *(const float4*)(xr + kc);       // broadcast LDS
            float4 x1 = *(const float4*)(xr + kc + 4);
            float4 e0 = *(const float4*)(e + kc);
            float4 e1 = *(const float4*)(e + kc + 4);
            d = fmaf(x0.x, e0.x, d); d = fmaf(x0.y, e0.y, d);
            d = fmaf(x0.z, e0.z, d); d = fmaf(x0.w, e0.w, d);
            d = fmaf(x1.x, e1.x, d); d = fmaf(x1.y, e1.y, d);
            d = fmaf(x1.z, e1.z, d); d = fmaf(x1.w, e1.w, d);
        }
        float x2 = g_x2[n];
        q = __fadd_rn(__fadd_rn(x2, -__fmul_rn(2.f, d)), g_w2[ss]);
        if (!active) { q = 3.4e38f; ss = SCODE; }
    } else {
        // fallback: full exact scan, lane strided (expected never)
        float x2 = g_x2[n];
        q = 3.4e38f; ss = SCODE;
        for (int s0 = lane; s0 < SCODE; s0 += 32) {
            const float* e = emb + (size_t)s0 * CDIM;
            float d = 0.f;
            for (int k = 0; k < CDIM; k++) d = fmaf(xr[k], e[k], d);
            float qq = __fadd_rn(__fadd_rn(x2, -__fmul_rn(2.f, d)), g_w2[s0]);
            if (qq < q || (qq == q && s0 < ss)) { q = qq; ss = s0; }
        }
    }
    // warp lex-min reduce on (q, ss): first-min (lowest index) tie-break
#pragma unroll
    for (int o = 16; o > 0; o >>= 1) {
        float q2 = __shfl_xor_sync(~0u, q, o);
        int   s2 = __shfl_xor_sync(~0u, ss, o);
        if (q2 < q || (q2 == q && s2 < ss)) { q = q2; ss = s2; }
    }
    if (lane == 0) {
        g_idx[n] = ss;
        atomicAdd(&g_hist[ss], 1u);
    }
}

// ======================= kernel: gather + ST write + loss ==================
__global__ void k_gather(const float* __restrict__ x, const float* __restrict__ emb,
                         float* __restrict__ out) {
    const int n0  = blockIdx.x * 64;
    const int b   = n0 >> 10;
    const int hw0 = n0 & 1023;
    const int tok = threadIdx.x & 63;
    const int cc  = threadIdx.x >> 6;

    const int mi = g_idx[n0 + tok];
    const float* e = emb + (size_t)mi * CDIM;
    const size_t base = (size_t)b * (CDIM * HW) + hw0 + tok;

    float s = 0.f;
    for (int c = cc; c < CDIM; c += 4) {
        float v = __ldg(e + c);
        size_t off = base + (size_t)c * HW;
        float xv = x[off];
        float diff = __fadd_rn(v, -xv);
        out[off] = __fadd_rn(xv, diff);
        s = fmaf(diff, diff, s);
    }
    __shared__ float red[256];
    red[threadIdx.x] = s;
    __syncthreads();
    for (int st = 128; st > 0; st >>= 1) {
        if (threadIdx.x < st) red[threadIdx.x] += red[threadIdx.x + st];
        __syncthreads();
    }
    if (threadIdx.x == 0) g_losspart[blockIdx.x] = red[0];
}

// ======================= kernel: finalize ==================================
__global__ void k_final(float* __restrict__ out, int out_size) {
    __shared__ float red[1024];
    const int t = threadIdx.x;
    float p = (float)g_hist[t] / (float)NTOK;
    red[t] = p * logf(p + 1e-6f);
    __syncthreads();
    for (int st = 512; st > 0; st >>= 1) {
        if (t < st) red[t] += red[t + st];
        __syncthreads();
    }
    float plogp = red[0];
    __syncthreads();
    red[t] = (t < 512) ? g_losspart[t] : 0.f;
    __syncthreads();
    for (int st = 512; st > 0; st >>= 1) {
        if (t < st) red[t] += red[t + st];
        __syncthreads();
    }
    if (t == 0) {
        out[out_size - 2] = BETA * (red[0] / (float)(NTOK * CDIM));
        out[out_size - 1] = expf(-plogp);
    }
}

// ======================= launch ============================================
extern "C" void kernel_launch(void* const* d_in, const int* in_sizes, int n_in,
                              void* d_out, int out_size) {
    const float* x   = (const float*)d_in[0];   // [32,256,32,32]
    const float* emb = (const float*)d_in[1];   // [1024,256]
    float* out = (float*)d_out;

    k_init<<<128, 256>>>(emb);
    k_pre<<<dim3(32, 32), 256>>>(x);

    cudaFuncSetAttribute(k_mma, cudaFuncAttributeMaxDynamicSharedMemorySize, SMEM_SZ);
    k_mma<<<NTOK / 128, 256, SMEM_SZ>>>();

    k_exact<<<NTOK / 8, 256>>>(x, emb);
    k_gather<<<NTOK / 64, 256>>>(x, emb, out);
    k_final<<<1, 1024>>>(out, out_size);
}

// round 16
// speedup vs baseline: 1.1239x; 1.0064x over previous
#include <cuda_runtime.h>
#include <cuda_bf16.h>
#include <math.h>
#include <stdint.h>

#define NTOK   32768
#define CDIM   256
#define SCODE  1024
#define HW     1024
#define BETA   0.25f

// certified bounds: |w| <= 2^-10, |w - bf16(w)| <= 2^-9 * 2^-10 = 2^-19
#define WMAX   9.765625e-4f
#define WLOMAX 1.9073486e-6f

// ======================= device scratch ====================================
__device__ float          g_w2[SCODE];
__device__ float          g_x2[NTOK];      // exact x2 (reference chain)
__device__ float          g_sa[NTOK];      // sum |x - bf16(x)|  (bound)
__device__ float          g_sh[NTOK];      // sum |bf16(x)|      (bound)
__device__ int            g_idx[NTOK];
__device__ unsigned int   g_hist[SCODE];
__device__ float          g_losspart[512];
__device__ __nv_bfloat16  g_xhi[NTOK * CDIM];   // [tok][k]
__device__ __nv_bfloat16  g_ehi[SCODE * CDIM];  // [code][k]
__device__ float          g_scores[(size_t)NTOK * SCODE];   // 128 MB
__device__ int            g_cand[NTOK * 16];
__device__ int            g_cnt [NTOK];

// ======================= small helpers =====================================
__device__ __forceinline__ uint32_t smem_u32(const void* p) {
    uint32_t a;
    asm("{ .reg .u64 t; cvta.to.shared.u64 t, %1; cvt.u32.u64 %0, t; }" : "=r"(a) : "l"(p));
    return a;
}
__device__ __forceinline__ void ldsm4(uint32_t& r0, uint32_t& r1, uint32_t& r2, uint32_t& r3,
                                      uint32_t addr) {
    asm volatile("ldmatrix.sync.aligned.m8n8.x4.shared.b16 {%0,%1,%2,%3}, [%4];"
                 : "=r"(r0), "=r"(r1), "=r"(r2), "=r"(r3) : "r"(addr));
}
__device__ __forceinline__ void mma16816(float* c, const uint32_t* a, uint32_t b0, uint32_t b1) {
    asm volatile("mma.sync.aligned.m16n8k16.row.col.f32.bf16.bf16.f32 "
                 "{%0,%1,%2,%3}, {%4,%5,%6,%7}, {%8,%9}, {%0,%1,%2,%3};"
                 : "+f"(c[0]), "+f"(c[1]), "+f"(c[2]), "+f"(c[3])
                 : "r"(a[0]), "r"(a[1]), "r"(a[2]), "r"(a[3]), "r"(b0), "r"(b1));
}
// swizzled byte offset in a [row][256 bf16] tile (512B rows, 16B granules)
__device__ __forceinline__ uint32_t swz(int row, int k) {   // k multiple of 8
    int ch = k >> 3;   // 0..31
    return (uint32_t)(row * 512 + ((ch >> 3) << 7) + (((ch & 7) ^ (row & 7)) << 4));
}
__device__ __forceinline__ float ulp_of(float v) {
    return __uint_as_float(__float_as_uint(v) & 0x7f800000u) * 1.1920929e-7f;
}

// ======================= kernel: init (w2 exact, zero, emb->bf16) ==========
// grid 128 x 256 = 32768 threads
__global__ void k_init(const float* __restrict__ emb) {
    int t = blockIdx.x * 256 + threadIdx.x;   // 0..32767
    // emb bf16 convert: 8 elements per thread
    {
        float4 a = *(const float4*)(emb + (size_t)t * 8);
        float4 b = *(const float4*)(emb + (size_t)t * 8 + 4);
        __nv_bfloat162 r[4];
        r[0] = __nv_bfloat162(__float2bfloat16(a.x), __float2bfloat16(a.y));
        r[1] = __nv_bfloat162(__float2bfloat16(a.z), __float2bfloat16(a.w));
        r[2] = __nv_bfloat162(__float2bfloat16(b.x), __float2bfloat16(b.y));
        r[3] = __nv_bfloat162(__float2bfloat16(b.z), __float2bfloat16(b.w));
        *(uint4*)(g_ehi + (size_t)t * 8) = *(uint4*)r;
    }
    if (t < SCODE) {
        const float* row = emb + (size_t)t * CDIM;
        float s = 0.f;
        for (int k = 0; k < CDIM; k++) s = __fadd_rn(s, __fmul_rn(row[k], row[k]));
        g_w2[t] = s;
        g_hist[t] = 0u;
    }
    if (t < 512) g_losspart[t] = 0.f;
}

// ======================= kernel: x prep (transpose, x2 exact, bounds) ======
// grid (32 hw-tiles, 32 batches), 256 threads. Block = 32 tokens x all 256 c.
__global__ void __launch_bounds__(256) k_pre(const float* __restrict__ x) {
    __shared__ float tile[256][33];          // [c][tok], pad 33 -> conflict-free
    __shared__ float psa[32][8], psh[32][8];
    const int tid = threadIdx.x;
    const int b = blockIdx.y, hw0 = blockIdx.x * 32;
    const int tok_base = b * HW + hw0;

    // load: warp w covers c = i*8 + w, 128B coalesced rows
    const float* xb = x + (size_t)b * CDIM * HW + hw0;
    const int wc = tid >> 5, lh = tid & 31;
#pragma unroll 8
    for (int i = 0; i < 32; i++)
        tile[i * 8 + wc][lh] = xb[(size_t)(i * 8 + wc) * HW + lh];
    __syncthreads();

    // bf16 transpose write + margin partials: 8 threads per token, 32 c each
    {
        const int tok = tid >> 3, c0 = (tid & 7) * 32;
        float sa = 0.f, sh = 0.f;
        __nv_bfloat16 hb[32];
#pragma unroll
        for (int j = 0; j < 32; j++) {
            float v = tile[c0 + j][tok];
            __nv_bfloat16 h = __float2bfloat16(v);
            float hf = __bfloat162float(h);
            hb[j] = h;
            sa += fabsf(v - hf);
            sh += fabsf(hf);
        }
        uint4* dst = (uint4*)(g_xhi + (size_t)(tok_base + tok) * CDIM + c0);
        const uint4* src = (const uint4*)hb;
#pragma unroll
        for (int j = 0; j < 4; j++) dst[j] = src[j];
        psa[tok][tid & 7] = sa;
        psh[tok][tid & 7] = sh;
    }
    __syncthreads();

    // exact x2 chain (reference order) per token, warp 0
    if (tid < 32) {
        float s = 0.f;
        for (int c = 0; c < CDIM; c++) {
            float v = tile[c][tid];
            s = __fadd_rn(s, __fmul_rn(v, v));
        }
        g_x2[tok_base + tid] = s;
        float a = 0.f, h = 0.f;
#pragma unroll
        for (int j = 0; j < 8; j++) { a += psa[tid][j]; h += psh[tid][j]; }
        g_sa[tok_base + tid] = a;
        g_sh[tok_base + tid] = h;
    }
}

// ======================= kernel: HMMA GEMM + min + candidate collect =======
// 256 blocks x 256 threads (8 warps); 128 tokens/block; 16 code tiles of 64.
#define SA    0
#define SB0   65536
#define SB1   98304
#define SW2   131072
#define SMIN  135168
#define SMEM_SZ 135680

__global__ void __launch_bounds__(256, 1) k_mma() {
    extern __shared__ char smem[];
    const uint32_t sb = smem_u32(smem);
    const int tid  = threadIdx.x;
    const int wid  = tid >> 5;
    const int lane = tid & 31;
    const int n0   = blockIdx.x * 128;
    const int tw   = wid * 16;                    // warp's token base within block
    float* w2s  = (float*)(smem + SW2);
    float* smin = (float*)(smem + SMIN);

    // load A (x_hi 128x256 bf16, swizzled)
#pragma unroll
    for (int i = 0; i < 16; i++) {
        int v = i * 256 + tid;                    // 0..4095
        int row = v >> 5, ch = v & 31;
        uint4 d = *(const uint4*)(g_xhi + (size_t)(n0 + row) * CDIM + ch * 8);
        *(uint4*)(smem + SA + swz(row, ch * 8)) = d;
    }
    // load B tile 0
#pragma unroll
    for (int i = 0; i < 8; i++) {
        int v = i * 256 + tid;                    // 0..2047
        int row = v >> 5, ch = v & 31;
        uint4 d = *(const uint4*)(g_ehi + (size_t)row * CDIM + ch * 8);
        *(uint4*)(smem + SB0 + swz(row, ch * 8)) = d;
    }
    // w2 -> smem, min init
#pragma unroll
    for (int i = 0; i < 4; i++) w2s[tid + i * 256] = g_w2[tid + i * 256];
    if (tid < 128) smin[tid] = 3.4e38f;
    __syncthreads();

    // ldmatrix lane addressing (constant per lane)
    const int arow = tw + (lane & 15);
    const int akof = (lane >> 4) << 3;
    const int brow = (lane & 7) + ((lane >> 4) << 3);   // + g*16
    const int bkof = ((lane >> 3) & 1) << 3;
    // epilogue addressing
    const int r4 = lane >> 2;            // 0..7
    const int c2 = (lane & 3) * 2;

    for (int t = 0; t < 16; t++) {
        char* B = smem + ((t & 1) ? SB1 : SB0);
        // stage next B tile into registers (hidden under compute)
        uint4 st[8];
        if (t < 15) {
#pragma unroll
            for (int i = 0; i < 8; i++) {
                int v = i * 256 + tid;
                int row = v >> 5, ch = v & 31;
                st[i] = *(const uint4*)(g_ehi + (size_t)((t + 1) * 64 + row) * CDIM + ch * 8);
            }
        }

        float acc[8][4];
#pragma unroll
        for (int g = 0; g < 8; g++)
#pragma unroll
            for (int j = 0; j < 4; j++) acc[g][j] = 0.f;

#pragma unroll
        for (int ks = 0; ks < 16; ks++) {
            uint32_t a[4];
            ldsm4(a[0], a[1], a[2], a[3], sb + SA + swz(arow, ks * 16 + akof));
#pragma unroll
            for (int g = 0; g < 4; g++) {
                uint32_t b0, b1, b2, b3;
                ldsm4(b0, b1, b2, b3,
                      sb + (uint32_t)(B - smem) + swz(g * 16 + brow, ks * 16 + bkof));
                mma16816(acc[2 * g],     a, b0, b1);
                mma16816(acc[2 * g + 1], a, b2, b3);
            }
        }

        // epilogue: s = w2 - 2*dot -> gmem scores + running per-token min
        {
            const int cb = t * 64;
            float* s0 = g_scores + (size_t)(n0 + tw + r4) * SCODE + cb;
            float* s1 = g_scores + (size_t)(n0 + tw + r4 + 8) * SCODE + cb;
            float m0 = 3.4e38f, m1 = 3.4e38f;
#pragma unroll
            for (int g = 0; g < 8; g++) {
                int col = g * 8 + c2;
                float w0 = w2s[cb + col], w1 = w2s[cb + col + 1];
                float2 v0 = { w0 - 2.f * acc[g][0], w1 - 2.f * acc[g][1] };
                float2 v1 = { w0 - 2.f * acc[g][2], w1 - 2.f * acc[g][3] };
                *(float2*)(s0 + col) = v0;
                *(float2*)(s1 + col) = v1;
                m0 = fminf(m0, fminf(v0.x, v0.y));
                m1 = fminf(m1, fminf(v1.x, v1.y));
            }
            // reduce over the 4 lanes sharing this r4
            m0 = fminf(m0, __shfl_xor_sync(~0u, m0, 1));
            m0 = fminf(m0, __shfl_xor_sync(~0u, m0, 2));
            m1 = fminf(m1, __shfl_xor_sync(~0u, m1, 1));
            m1 = fminf(m1, __shfl_xor_sync(~0u, m1, 2));
            if ((lane & 3) == 0) {
                smin[tw + r4]     = fminf(smin[tw + r4], m0);
                smin[tw + r4 + 8] = fminf(smin[tw + r4 + 8], m1);
            }
        }

        // commit staged B, barrier
        if (t < 15) {
            char* Bn = smem + ((t & 1) ? SB0 : SB1);
#pragma unroll
            for (int i = 0; i < 8; i++) {
                int v = i * 256 + tid;
                int row = v >> 5, ch = v & 31;
                *(uint4*)(Bn + swz(row, ch * 8)) = st[i];
            }
            __syncthreads();
        }
    }
    __syncthreads();   // scores + smin visible block-wide

    // phase 2: candidate collection vs final min (scores mostly L2-hot)
    for (int i = 0; i < 16; i++) {
        const int tok = tw + i;
        const int n = n0 + tok;
        float x2 = g_x2[n];
        float gg = ulp_of(x2 + 0.25f);
        float marg = 2.f * gg + 2.004f * (WMAX * g_sa[n] + WLOMAX * g_sh[n]) + 1e-5f;
        const float thr = smin[tok] + marg;
        const float4* sp = (const float4*)(g_scores + (size_t)n * SCODE);
        int cnt = 0;
#pragma unroll
        for (int c = 0; c < 8; c++) {
            float4 v = sp[c * 32 + lane];
            float vv[4] = {v.x, v.y, v.z, v.w};
#pragma unroll
            for (int q = 0; q < 4; q++) {
                bool p = vv[q] < thr;
                unsigned m = __ballot_sync(~0u, p);
                if (p) {
                    int pos = cnt + __popc(m & ((1u << lane) - 1u));
                    if (pos < 16) g_cand[(size_t)n * 16 + pos] = c * 128 + lane * 4 + q;
                }
                cnt += __popc(m);
            }
        }
        if (lane == 0) g_cnt[n] = (cnt > 16) ? 1000 : cnt;
    }
}

// ======================= kernel: exact recompute, warp-per-token ===========
// x staged via smem (full-sector coalesced loads, broadcast reads);
// lane l owns candidate l; INACTIVE LANES DO NO LOADS (predicated loop).
__global__ void __launch_bounds__(256) k_exact(const float* __restrict__ x,
                                               const float* __restrict__ emb) {
    __shared__ float sx[8][256];
    const int tid = threadIdx.x;
    const int wid = tid >> 5;
    const int lane = tid & 31;
    const int nb = blockIdx.x * 8;            // 8 consecutive tokens (same batch)
    const int b = nb >> 10, hw0 = nb & 1023;

    // stage x: thread c loads x[b, c, hw0..hw0+7] (one full 32B sector)
    {
        const float* xp = x + ((size_t)b * CDIM + tid) * HW + hw0;
        float4 v0 = *(const float4*)(xp);
        float4 v1 = *(const float4*)(xp + 4);
        sx[0][tid] = v0.x; sx[1][tid] = v0.y; sx[2][tid] = v0.z; sx[3][tid] = v0.w;
        sx[4][tid] = v1.x; sx[5][tid] = v1.y; sx[6][tid] = v1.z; sx[7][tid] = v1.w;
    }
    __syncthreads();

    const int n = nb + wid;
    const float* xr = sx[wid];
    const int cnt = g_cnt[n];
    float q = 3.4e38f; int ss = SCODE;

    if (cnt <= 16) {
        if (lane < cnt) {       // inactive lanes: zero loads, zero FMAs
            ss = g_cand[(size_t)n * 16 + lane];
            const float* e = emb + (size_t)ss * CDIM;
            float d = 0.f;
            for (int kc = 0; kc < CDIM; kc += 8) {
                float4 x0 = *(const float4*)(xr + kc);       // broadcast LDS
                float4 x1 = *(const float4*)(xr + kc + 4);
                float4 e0 = *(const float4*)(e + kc);
                float4 e1 = *(const float4*)(e + kc + 4);
                d = fmaf(x0.x, e0.x, d); d = fmaf(x0.y, e0.y, d);
                d = fmaf(x0.z, e0.z, d); d = fmaf(x0.w, e0.w, d);
                d = fmaf(x1.x, e1.x, d); d = fmaf(x1.y, e1.y, d);
                d = fmaf(x1.z, e1.z, d); d = fmaf(x1.w, e1.w, d);
            }
            float x2 = g_x2[n];
            q = __fadd_rn(__fadd_rn(x2, -__fmul_rn(2.f, d)), g_w2[ss]);
        }
    } else {
        // fallback: full exact scan, lane strided (expected never)
        float x2 = g_x2[n];
        for (int s0 = lane; s0 < SCODE; s0 += 32) {
            const float* e = emb + (size_t)s0 * CDIM;
            float d = 0.f;
            for (int k = 0; k < CDIM; k++) d = fmaf(xr[k], e[k], d);
            float qq = __fadd_rn(__fadd_rn(x2, -__fmul_rn(2.f, d)), g_w2[s0]);
            if (qq < q || (qq == q && s0 < ss)) { q = qq; ss = s0; }
        }
    }
    // warp lex-min reduce on (q, ss): first-min (lowest index) tie-break
#pragma unroll
    for (int o = 16; o > 0; o >>= 1) {
        float q2 = __shfl_xor_sync(~0u, q, o);
        int   s2 = __shfl_xor_sync(~0u, ss, o);
        if (q2 < q || (q2 == q && s2 < ss)) { q = q2; ss = s2; }
    }
    if (lane == 0) {
        g_idx[n] = ss;
        atomicAdd(&g_hist[ss], 1u);
    }
}

// ======================= kernel: gather + ST write + loss ==================
__global__ void k_gather(const float* __restrict__ x, const float* __restrict__ emb,
                         float* __restrict__ out) {
    const int n0  = blockIdx.x * 64;
    const int b   = n0 >> 10;
    const int hw0 = n0 & 1023;
    const int tok = threadIdx.x & 63;
    const int cc  = threadIdx.x >> 6;

    const int mi = g_idx[n0 + tok];
    const float* e = emb + (size_t)mi * CDIM;
    const size_t base = (size_t)b * (CDIM * HW) + hw0 + tok;

    float s = 0.f;
    for (int c = cc; c < CDIM; c += 4) {
        float v = __ldg(e + c);
        size_t off = base + (size_t)c * HW;
        float xv = x[off];
        float diff = __fadd_rn(v, -xv);
        out[off] = __fadd_rn(xv, diff);
        s = fmaf(diff, diff, s);
    }
    __shared__ float red[256];
    red[threadIdx.x] = s;
    __syncthreads();
    for (int st = 128; st > 0; st >>= 1) {
        if (threadIdx.x < st) red[threadIdx.x] += red[threadIdx.x + st];
        __syncthreads();
    }
    if (threadIdx.x == 0) g_losspart[blockIdx.x] = red[0];
}

// ======================= kernel: finalize ==================================
__global__ void k_final(float* __restrict__ out, int out_size) {
    __shared__ float red[1024];
    const int t = threadIdx.x;
    float p = (float)g_hist[t] / (float)NTOK;
    red[t] = p * logf(p + 1e-6f);
    __syncthreads();
    for (int st = 512; st > 0; st >>= 1) {
        if (t < st) red[t] += red[t + st];
        __syncthreads();
    }
    float plogp = red[0];
    __syncthreads();
    red[t] = (t < 512) ? g_losspart[t] : 0.f;
    __syncthreads();
    for (int st = 512; st > 0; st >>= 1) {
        if (t < st) red[t] += red[t + st];
        __syncthreads();
    }
    if (t == 0) {
        out[out_size - 2] = BETA * (red[0] / (float)(NTOK * CDIM));
        out[out_size - 1] = expf(-plogp);
    }
}

// ======================= launch ============================================
extern "C" void kernel_launch(void* const* d_in, const int* in_sizes, int n_in,
                              void* d_out, int out_size) {
    const float* x   = (const float*)d_in[0];   // [32,256,32,32]
    const float* emb = (const float*)d_in[1];   // [1024,256]
    float* out = (float*)d_out;

    k_init<<<128, 256>>>(emb);
    k_pre<<<dim3(32, 32), 256>>>(x);

    cudaFuncSetAttribute(k_mma, cudaFuncAttributeMaxDynamicSharedMemorySize, SMEM_SZ);
    k_mma<<<NTOK / 128, 256, SMEM_SZ>>>();

    k_exact<<<NTOK / 8, 256>>>(x, emb);
    k_gather<<<NTOK / 64, 256>>>(x, emb, out);
    k_final<<<1, 1024>>>(out, out_size);
}

// round 17
// speedup vs baseline: 1.1789x; 1.0489x over previous
#include <cuda_runtime.h>
#include <cuda_bf16.h>
#include <math.h>
#include <stdint.h>

#define NTOK   32768
#define CDIM   256
#define SCODE  1024
#define HW     1024
#define BETA   0.25f

// certified bounds: |w| <= 2^-10, |w - bf16(w)| <= 2^-9 * 2^-10 = 2^-19
#define WMAX   9.765625e-4f
#define WLOMAX 1.9073486e-6f

// ======================= device scratch ====================================
__device__ float          g_w2[SCODE];
__device__ float          g_x2[NTOK];      // exact x2 (reference chain)
__device__ float          g_sa[NTOK];      // sum |x - bf16(x)|  (bound)
__device__ float          g_sh[NTOK];      // sum |bf16(x)|      (bound)
__device__ int            g_idx[NTOK];
__device__ unsigned int   g_hist[SCODE];
__device__ float          g_losspart[512];
__device__ __nv_bfloat16  g_xhi[NTOK * CDIM];   // [tok][k]
__device__ __nv_bfloat16  g_ehi[SCODE * CDIM];  // [code][k]
__device__ float          g_scores[(size_t)NTOK * SCODE];   // 128 MB
__device__ int            g_cand[NTOK * 16];
__device__ int            g_cnt [NTOK];

// ======================= small helpers =====================================
__device__ __forceinline__ uint32_t smem_u32(const void* p) {
    uint32_t a;
    asm("{ .reg .u64 t; cvta.to.shared.u64 t, %1; cvt.u32.u64 %0, t; }" : "=r"(a) : "l"(p));
    return a;
}
__device__ __forceinline__ void ldsm4(uint32_t& r0, uint32_t& r1, uint32_t& r2, uint32_t& r3,
                                      uint32_t addr) {
    asm volatile("ldmatrix.sync.aligned.m8n8.x4.shared.b16 {%0,%1,%2,%3}, [%4];"
                 : "=r"(r0), "=r"(r1), "=r"(r2), "=r"(r3) : "r"(addr));
}
__device__ __forceinline__ void mma16816(float* c, const uint32_t* a, uint32_t b0, uint32_t b1) {
    asm volatile("mma.sync.aligned.m16n8k16.row.col.f32.bf16.bf16.f32 "
                 "{%0,%1,%2,%3}, {%4,%5,%6,%7}, {%8,%9}, {%0,%1,%2,%3};"
                 : "+f"(c[0]), "+f"(c[1]), "+f"(c[2]), "+f"(c[3])
                 : "r"(a[0]), "r"(a[1]), "r"(a[2]), "r"(a[3]), "r"(b0), "r"(b1));
}
// swizzled byte offset in a [row][256 bf16] tile (512B rows, 16B granules)
__device__ __forceinline__ uint32_t swz(int row, int k) {   // k multiple of 8
    int ch = k >> 3;   // 0..31
    return (uint32_t)(row * 512 + ((ch >> 3) << 7) + (((ch & 7) ^ (row & 7)) << 4));
}
__device__ __forceinline__ float ulp_of(float v) {
    return __uint_as_float(__float_as_uint(v) & 0x7f800000u) * 1.1920929e-7f;
}

// ======================= kernel: init (w2 exact, zero, emb->bf16) ==========
// grid 128 x 256 = 32768 threads
__global__ void k_init(const float* __restrict__ emb) {
    int t = blockIdx.x * 256 + threadIdx.x;   // 0..32767
    // emb bf16 convert: 8 elements per thread
    {
        float4 a = *(const float4*)(emb + (size_t)t * 8);
        float4 b = *(const float4*)(emb + (size_t)t * 8 + 4);
        __nv_bfloat162 r[4];
        r[0] = __nv_bfloat162(__float2bfloat16(a.x), __float2bfloat16(a.y));
        r[1] = __nv_bfloat162(__float2bfloat16(a.z), __float2bfloat16(a.w));
        r[2] = __nv_bfloat162(__float2bfloat16(b.x), __float2bfloat16(b.y));
        r[3] = __nv_bfloat162(__float2bfloat16(b.z), __float2bfloat16(b.w));
        *(uint4*)(g_ehi + (size_t)t * 8) = *(uint4*)r;
    }
    if (t < SCODE) {
        const float* row = emb + (size_t)t * CDIM;
        float s = 0.f;
        for (int k = 0; k < CDIM; k++) s = __fadd_rn(s, __fmul_rn(row[k], row[k]));
        g_w2[t] = s;
        g_hist[t] = 0u;
    }
    if (t < 512) g_losspart[t] = 0.f;
}

// ======================= kernel: x prep (transpose, x2 exact, bounds) ======
// grid (32 hw-tiles, 32 batches), 256 threads. Block = 32 tokens x all 256 c.
__global__ void __launch_bounds__(256) k_pre(const float* __restrict__ x) {
    __shared__ float tile[256][33];          // [c][tok], pad 33 -> conflict-free
    __shared__ float psa[32][8], psh[32][8];
    const int tid = threadIdx.x;
    const int b = blockIdx.y, hw0 = blockIdx.x * 32;
    const int tok_base = b * HW + hw0;

    // load: warp w covers c = i*8 + w, 128B coalesced rows
    const float* xb = x + (size_t)b * CDIM * HW + hw0;
    const int wc = tid >> 5, lh = tid & 31;
#pragma unroll 8
    for (int i = 0; i < 32; i++)
        tile[i * 8 + wc][lh] = xb[(size_t)(i * 8 + wc) * HW + lh];
    __syncthreads();

    // bf16 transpose write + margin partials: 8 threads per token, 32 c each
    {
        const int tok = tid >> 3, c0 = (tid & 7) * 32;
        float sa = 0.f, sh = 0.f;
        __nv_bfloat16 hb[32];
#pragma unroll
        for (int j = 0; j < 32; j++) {
            float v = tile[c0 + j][tok];
            __nv_bfloat16 h = __float2bfloat16(v);
            float hf = __bfloat162float(h);
            hb[j] = h;
            sa += fabsf(v - hf);
            sh += fabsf(hf);
        }
        uint4* dst = (uint4*)(g_xhi + (size_t)(tok_base + tok) * CDIM + c0);
        const uint4* src = (const uint4*)hb;
#pragma unroll
        for (int j = 0; j < 4; j++) dst[j] = src[j];
        psa[tok][tid & 7] = sa;
        psh[tok][tid & 7] = sh;
    }
    __syncthreads();

    // exact x2 chain (reference order) per token, warp 0
    if (tid < 32) {
        float s = 0.f;
        for (int c = 0; c < CDIM; c++) {
            float v = tile[c][tid];
            s = __fadd_rn(s, __fmul_rn(v, v));
        }
        g_x2[tok_base + tid] = s;
        float a = 0.f, h = 0.f;
#pragma unroll
        for (int j = 0; j < 8; j++) { a += psa[tid][j]; h += psh[tid][j]; }
        g_sa[tok_base + tid] = a;
        g_sh[tok_base + tid] = h;
    }
}

// ======================= kernel: HMMA GEMM + min + candidate collect =======
// 256 blocks x 256 threads (8 warps); 128 tokens/block; 16 code tiles of 64.
#define SA    0
#define SB0   65536
#define SB1   98304
#define SW2   131072
#define SMIN  135168
#define SMEM_SZ 135680

__global__ void __launch_bounds__(256, 1) k_mma() {
    extern __shared__ char smem[];
    const uint32_t sb = smem_u32(smem);
    const int tid  = threadIdx.x;
    const int wid  = tid >> 5;
    const int lane = tid & 31;
    const int n0   = blockIdx.x * 128;
    const int tw   = wid * 16;                    // warp's token base within block
    float* w2s  = (float*)(smem + SW2);
    float* smin = (float*)(smem + SMIN);

    // load A (x_hi 128x256 bf16, swizzled)
#pragma unroll
    for (int i = 0; i < 16; i++) {
        int v = i * 256 + tid;                    // 0..4095
        int row = v >> 5, ch = v & 31;
        uint4 d = *(const uint4*)(g_xhi + (size_t)(n0 + row) * CDIM + ch * 8);
        *(uint4*)(smem + SA + swz(row, ch * 8)) = d;
    }
    // load B tile 0
#pragma unroll
    for (int i = 0; i < 8; i++) {
        int v = i * 256 + tid;                    // 0..2047
        int row = v >> 5, ch = v & 31;
        uint4 d = *(const uint4*)(g_ehi + (size_t)row * CDIM + ch * 8);
        *(uint4*)(smem + SB0 + swz(row, ch * 8)) = d;
    }
    // w2 -> smem, min init
#pragma unroll
    for (int i = 0; i < 4; i++) w2s[tid + i * 256] = g_w2[tid + i * 256];
    if (tid < 128) smin[tid] = 3.4e38f;
    __syncthreads();

    // ldmatrix lane addressing (constant per lane)
    const int arow = tw + (lane & 15);
    const int akof = (lane >> 4) << 3;
    const int brow = (lane & 7) + ((lane >> 4) << 3);   // + g*16
    const int bkof = ((lane >> 3) & 1) << 3;
    // epilogue addressing
    const int r4 = lane >> 2;            // 0..7
    const int c2 = (lane & 3) * 2;

    for (int t = 0; t < 16; t++) {
        char* B = smem + ((t & 1) ? SB1 : SB0);
        // stage next B tile into registers (hidden under compute)
        uint4 st[8];
        if (t < 15) {
#pragma unroll
            for (int i = 0; i < 8; i++) {
                int v = i * 256 + tid;
                int row = v >> 5, ch = v & 31;
                st[i] = *(const uint4*)(g_ehi + (size_t)((t + 1) * 64 + row) * CDIM + ch * 8);
            }
        }

        float acc[8][4];
#pragma unroll
        for (int g = 0; g < 8; g++)
#pragma unroll
            for (int j = 0; j < 4; j++) acc[g][j] = 0.f;

#pragma unroll
        for (int ks = 0; ks < 16; ks++) {
            uint32_t a[4];
            ldsm4(a[0], a[1], a[2], a[3], sb + SA + swz(arow, ks * 16 + akof));
#pragma unroll
            for (int g = 0; g < 4; g++) {
                uint32_t b0, b1, b2, b3;
                ldsm4(b0, b1, b2, b3,
                      sb + (uint32_t)(B - smem) + swz(g * 16 + brow, ks * 16 + bkof));
                mma16816(acc[2 * g],     a, b0, b1);
                mma16816(acc[2 * g + 1], a, b2, b3);
            }
        }

        // epilogue: s = w2 - 2*dot -> gmem scores + running per-token min
        {
            const int cb = t * 64;
            float* s0 = g_scores + (size_t)(n0 + tw + r4) * SCODE + cb;
            float* s1 = g_scores + (size_t)(n0 + tw + r4 + 8) * SCODE + cb;
            float m0 = 3.4e38f, m1 = 3.4e38f;
#pragma unroll
            for (int g = 0; g < 8; g++) {
                int col = g * 8 + c2;
                float w0 = w2s[cb + col], w1 = w2s[cb + col + 1];
                float2 v0 = { w0 - 2.f * acc[g][0], w1 - 2.f * acc[g][1] };
                float2 v1 = { w0 - 2.f * acc[g][2], w1 - 2.f * acc[g][3] };
                *(float2*)(s0 + col) = v0;
                *(float2*)(s1 + col) = v1;
                m0 = fminf(m0, fminf(v0.x, v0.y));
                m1 = fminf(m1, fminf(v1.x, v1.y));
            }
            // reduce over the 4 lanes sharing this r4
            m0 = fminf(m0, __shfl_xor_sync(~0u, m0, 1));
            m0 = fminf(m0, __shfl_xor_sync(~0u, m0, 2));
            m1 = fminf(m1, __shfl_xor_sync(~0u, m1, 1));
            m1 = fminf(m1, __shfl_xor_sync(~0u, m1, 2));
            if ((lane & 3) == 0) {
                smin[tw + r4]     = fminf(smin[tw + r4], m0);
                smin[tw + r4 + 8] = fminf(smin[tw + r4 + 8], m1);
            }
        }

        // commit staged B, barrier
        if (t < 15) {
            char* Bn = smem + ((t & 1) ? SB0 : SB1);
#pragma unroll
            for (int i = 0; i < 8; i++) {
                int v = i * 256 + tid;
                int row = v >> 5, ch = v & 31;
                *(uint4*)(Bn + swz(row, ch * 8)) = st[i];
            }
            __syncthreads();
        }
    }
    __syncthreads();   // scores + smin visible block-wide

    // phase 2: candidate collection vs final min (scores mostly L2-hot)
    for (int i = 0; i < 16; i++) {
        const int tok = tw + i;
        const int n = n0 + tok;
        float x2 = g_x2[n];
        float gg = ulp_of(x2 + 0.25f);
        float marg = 2.f * gg + 2.004f * (WMAX * g_sa[n] + WLOMAX * g_sh[n]) + 1e-5f;
        const float thr = smin[tok] + marg;
        const float4* sp = (const float4*)(g_scores + (size_t)n * SCODE);
        int cnt = 0;
#pragma unroll
        for (int c = 0; c < 8; c++) {
            float4 v = sp[c * 32 + lane];
            float vv[4] = {v.x, v.y, v.z, v.w};
#pragma unroll
            for (int q = 0; q < 4; q++) {
                bool p = vv[q] < thr;
                unsigned m = __ballot_sync(~0u, p);
                if (p) {
                    int pos = cnt + __popc(m & ((1u << lane) - 1u));
                    if (pos < 16) g_cand[(size_t)n * 16 + pos] = c * 128 + lane * 4 + q;
                }
                cnt += __popc(m);
            }
        }
        if (lane == 0) g_cnt[n] = (cnt > 16) ? 1000 : cnt;
    }
}

// ======================= kernel: exact recompute, smem-staged ==============
// Candidate e-rows preloaded to smem cooperatively; chains run on LDS only.
#define MAXROWS 32
#define SE_PITCH 260      // floats; bank = (slot*4 + k) % 32 -> conflict-free

__global__ void __launch_bounds__(256) k_exact(const float* __restrict__ x,
                                               const float* __restrict__ emb) {
    __shared__ float sx[8][256];              // x rows (broadcast reads)
    __shared__ float se[MAXROWS * SE_PITCH];  // candidate e-rows
    __shared__ int   s_cnt[8], s_off[9], s_cs[MAXROWS];
    const int tid = threadIdx.x;
    const int wid = tid >> 5;
    const int lane = tid & 31;
    const int nb = blockIdx.x * 8;            // 8 consecutive tokens (same batch)
    const int b = nb >> 10, hw0 = nb & 1023;

    // stage x: thread c loads x[b, c, hw0..hw0+7] (one full 32B sector)
    {
        const float* xp = x + ((size_t)b * CDIM + tid) * HW + hw0;
        float4 v0 = *(const float4*)(xp);
        float4 v1 = *(const float4*)(xp + 4);
        sx[0][tid] = v0.x; sx[1][tid] = v0.y; sx[2][tid] = v0.z; sx[3][tid] = v0.w;
        sx[4][tid] = v1.x; sx[5][tid] = v1.y; sx[6][tid] = v1.z; sx[7][tid] = v1.w;
    }
    // prefix offsets (thread 0)
    if (tid == 0) {
        int P = 0;
#pragma unroll
        for (int t = 0; t < 8; t++) {
            int c = g_cnt[nb + t];
            s_cnt[t] = c;
            s_off[t] = P;
            P += (c <= 16) ? c : 0;
        }
        s_off[8] = P;
    }
    __syncthreads();

    // compaction: warp w = token w; lane l < cnt writes its cand id
    const int cnt = s_cnt[wid];
    int myss = SCODE;
    if (cnt <= 16 && lane < cnt) {
        myss = g_cand[(size_t)(nb + wid) * 16 + lane];
        int slot = s_off[wid] + lane;
        if (slot < MAXROWS) s_cs[slot] = myss;
    }
    __syncthreads();

    // cooperative preload of candidate e-rows (coalesced float4)
    {
        const int P = min(s_off[8], MAXROWS);
        for (int i = tid; i < P * 64; i += 256) {
            int p = i >> 6, k4 = (i & 63) << 2;
            float4 v = *(const float4*)(emb + (size_t)s_cs[p] * CDIM + k4);
            *(float4*)(se + p * SE_PITCH + k4) = v;
        }
    }
    __syncthreads();

    const int n = nb + wid;
    const float* xr = sx[wid];
    float q = 3.4e38f; int ss = SCODE;

    if (cnt <= 16) {
        if (lane < cnt) {
            ss = myss;
            const int slot = s_off[wid] + lane;
            float d = 0.f;
            if (slot < MAXROWS) {
                const float* e = se + slot * SE_PITCH;
#pragma unroll 4
                for (int kc = 0; kc < CDIM; kc += 8) {
                    float4 x0 = *(const float4*)(xr + kc);
                    float4 x1 = *(const float4*)(xr + kc + 4);
                    float4 e0 = *(const float4*)(e + kc);
                    float4 e1 = *(const float4*)(e + kc + 4);
                    d = fmaf(x0.x, e0.x, d); d = fmaf(x0.y, e0.y, d);
                    d = fmaf(x0.z, e0.z, d); d = fmaf(x0.w, e0.w, d);
                    d = fmaf(x1.x, e1.x, d); d = fmaf(x1.y, e1.y, d);
                    d = fmaf(x1.z, e1.z, d); d = fmaf(x1.w, e1.w, d);
                }
            } else {            // smem overflow (rare): direct gmem loads
                const float* e = emb + (size_t)ss * CDIM;
                for (int kc = 0; kc < CDIM; kc += 8) {
                    float4 x0 = *(const float4*)(xr + kc);
                    float4 x1 = *(const float4*)(xr + kc + 4);
                    float4 e0 = *(const float4*)(e + kc);
                    float4 e1 = *(const float4*)(e + kc + 4);
                    d = fmaf(x0.x, e0.x, d); d = fmaf(x0.y, e0.y, d);
                    d = fmaf(x0.z, e0.z, d); d = fmaf(x0.w, e0.w, d);
                    d = fmaf(x1.x, e1.x, d); d = fmaf(x1.y, e1.y, d);
                    d = fmaf(x1.z, e1.z, d); d = fmaf(x1.w, e1.w, d);
                }
            }
            float x2 = g_x2[n];
            q = __fadd_rn(__fadd_rn(x2, -__fmul_rn(2.f, d)), g_w2[ss]);
        }
    } else {
        // fallback: full exact scan, lane strided (expected never)
        float x2 = g_x2[n];
        for (int s0 = lane; s0 < SCODE; s0 += 32) {
            const float* e = emb + (size_t)s0 * CDIM;
            float d = 0.f;
            for (int k = 0; k < CDIM; k++) d = fmaf(xr[k], e[k], d);
            float qq = __fadd_rn(__fadd_rn(x2, -__fmul_rn(2.f, d)), g_w2[s0]);
            if (qq < q || (qq == q && s0 < ss)) { q = qq; ss = s0; }
        }
    }
    // warp lex-min reduce on (q, ss): first-min (lowest index) tie-break
#pragma unroll
    for (int o = 16; o > 0; o >>= 1) {
        float q2 = __shfl_xor_sync(~0u, q, o);
        int   s2 = __shfl_xor_sync(~0u, ss, o);
        if (q2 < q || (q2 == q && s2 < ss)) { q = q2; ss = s2; }
    }
    if (lane == 0) {
        g_idx[n] = ss;
        atomicAdd(&g_hist[ss], 1u);
    }
}

// ======================= kernel: gather + ST write + loss ==================
__global__ void k_gather(const float* __restrict__ x, const float* __restrict__ emb,
                         float* __restrict__ out) {
    const int n0  = blockIdx.x * 64;
    const int b   = n0 >> 10;
    const int hw0 = n0 & 1023;
    const int tok = threadIdx.x & 63;
    const int cc  = threadIdx.x >> 6;

    const int mi = g_idx[n0 + tok];
    const float* e = emb + (size_t)mi * CDIM;
    const size_t base = (size_t)b * (CDIM * HW) + hw0 + tok;

    float s = 0.f;
    for (int c = cc; c < CDIM; c += 4) {
        float v = __ldg(e + c);
        size_t off = base + (size_t)c * HW;
        float xv = x[off];
        float diff = __fadd_rn(v, -xv);
        out[off] = __fadd_rn(xv, diff);
        s = fmaf(diff, diff, s);
    }
    __shared__ float red[256];
    red[threadIdx.x] = s;
    __syncthreads();
    for (int st = 128; st > 0; st >>= 1) {
        if (threadIdx.x < st) red[threadIdx.x] += red[threadIdx.x + st];
        __syncthreads();
    }
    if (threadIdx.x == 0) g_losspart[blockIdx.x] = red[0];
}

// ======================= kernel: finalize ==================================
__global__ void k_final(float* __restrict__ out, int out_size) {
    __shared__ float red[1024];
    const int t = threadIdx.x;
    float p = (float)g_hist[t] / (float)NTOK;
    red[t] = p * logf(p + 1e-6f);
    __syncthreads();
    for (int st = 512; st > 0; st >>= 1) {
        if (t < st) red[t] += red[t + st];
        __syncthreads();
    }
    float plogp = red[0];
    __syncthreads();
    red[t] = (t < 512) ? g_losspart[t] : 0.f;
    __syncthreads();
    for (int st = 512; st > 0; st >>= 1) {
        if (t < st) red[t] += red[t + st];
        __syncthreads();
    }
    if (t == 0) {
        out[out_size - 2] = BETA * (red[0] / (float)(NTOK * CDIM));
        out[out_size - 1] = expf(-plogp);
    }
}

// ======================= launch ============================================
extern "C" void kernel_launch(void* const* d_in, const int* in_sizes, int n_in,
                              void* d_out, int out_size) {
    const float* x   = (const float*)d_in[0];   // [32,256,32,32]
    const float* emb = (const float*)d_in[1];   // [1024,256]
    float* out = (float*)d_out;

    k_init<<<128, 256>>>(emb);
    k_pre<<<dim3(32, 32), 256>>>(x);

    cudaFuncSetAttribute(k_mma, cudaFuncAttributeMaxDynamicSharedMemorySize, SMEM_SZ);
    k_mma<<<NTOK / 128, 256, SMEM_SZ>>>();

    k_exact<<<NTOK / 8, 256>>>(x, emb);
    k_gather<<<NTOK / 64, 256>>>(x, emb, out);
    k_final<<<1, 1024>>>(out, out_size);
}